// round 1
// baseline (speedup 1.0000x reference)
#include <cuda_runtime.h>
#include <cuda_fp16.h>

// Problem dims
#define T_  512
#define B_  128
#define D_  128
#define H_  512
#define O_  128
#define G4H 2048

#define NL    64          // CTAs per layer
#define NCTA  128         // total persistent CTAs (64 layer0 + 64 layer1)
#define NJ    8           // h-columns per CTA
#define NGC   32          // gate columns per CTA (4*NJ)

// ---------------- static device buffers (sanctioned scratch) ----------------
__device__ __align__(16) __half  g_xT[T_ * B_ * D_];          // x transposed [t][b][d], fp16
__device__ __align__(16) __half  g_W0[G4H * 640];             // [n][k]: k<128 = w_ih_0, else w_hh_0
__device__ __align__(16) __half  g_W1[G4H * 1024];            // [n][k]: k<512 = w_ih_1, else w_hh_1
__device__ __align__(16) __half  g_h0buf[2 * B_ * H_];        // double-buffered layer0 h
__device__ __align__(16) __half  g_h1seq[(T_ + 1) * B_ * H_]; // [t+1][b][k]; [0] = init
__device__ __align__(16) __half  g_Wout[O_ * H_];             // [o][k]
__device__ unsigned g_bar_count;
__device__ unsigned g_bar_phase;

// ---------------- helpers ----------------
__device__ __forceinline__ void mma_f16(float* c, const unsigned* a, const unsigned* b) {
    asm volatile(
        "mma.sync.aligned.m16n8k16.row.col.f32.f16.f16.f32 "
        "{%0,%1,%2,%3}, {%4,%5,%6,%7}, {%8,%9}, {%0,%1,%2,%3};"
        : "+f"(c[0]), "+f"(c[1]), "+f"(c[2]), "+f"(c[3])
        : "r"(a[0]), "r"(a[1]), "r"(a[2]), "r"(a[3]), "r"(b[0]), "r"(b[1]));
}
__device__ __forceinline__ void cp16(void* sdst, const void* gsrc) {
    unsigned s = (unsigned)__cvta_generic_to_shared(sdst);
    asm volatile("cp.async.cg.shared.global [%0], [%1], 16;" :: "r"(s), "l"(gsrc));
}
__device__ __forceinline__ void cp_commit() { asm volatile("cp.async.commit_group;"); }
__device__ __forceinline__ void cp_wait1()  { asm volatile("cp.async.wait_group 1;"); }
__device__ __forceinline__ void cp_wait0()  { asm volatile("cp.async.wait_group 0;"); }

__device__ __forceinline__ float sigf(float x) { return 1.0f / (1.0f + __expf(-x)); }

// ---------------- prep: layout conversion + barrier reset ----------------
__global__ void __launch_bounds__(256) lstm86_prep(
    const float* __restrict__ x, const float* __restrict__ h0,
    const float* __restrict__ wih0, const float* __restrict__ whh0,
    const float* __restrict__ wih1, const float* __restrict__ whh1,
    const float* __restrict__ wout)
{
    const int tid = blockIdx.x * blockDim.x + threadIdx.x;
    const int nt  = gridDim.x * blockDim.x;

    for (int i = tid; i < T_ * B_ * D_; i += nt) {
        int t = i >> 14; int r = i & 16383; int b = r >> 7; int d = r & 127;
        g_xT[i] = __float2half(x[(size_t)b * (T_ * D_) + t * D_ + d]);
    }
    for (int i = tid; i < G4H * 640; i += nt) {
        int n = i / 640, k = i - n * 640;
        float v = (k < 128) ? wih0[n * 128 + k] : whh0[n * 512 + (k - 128)];
        g_W0[i] = __float2half(v);
    }
    for (int i = tid; i < G4H * 1024; i += nt) {
        int n = i >> 10, k = i & 1023;
        float v = (k < 512) ? wih1[n * 512 + k] : whh1[n * 512 + (k - 512)];
        g_W1[i] = __float2half(v);
    }
    for (int i = tid; i < O_ * H_; i += nt) g_Wout[i] = __float2half(wout[i]);
    for (int i = tid; i < B_ * H_; i += nt) {
        g_h0buf[B_ * H_ + i] = __float2half(h0[i]);          // buffer 1 = layer0 init h
        g_h1seq[i]           = __float2half(h0[B_ * H_ + i]); // h1seq[0] = layer1 init h
    }
    if (tid == 0) { g_bar_count = 0; g_bar_phase = 0; }
}

// ---------------- persistent recurrent kernel ----------------
template <int LAYER>
__device__ __forceinline__ void lstm86_role(int q, const float* __restrict__ c0, char* smem)
{
    constexpr int K  = (LAYER == 0) ? 640 : 1024;
    constexpr int NC = K / 64;        // chunks of 64 along K
    constexpr int WP = K + 8;         // padded smem row stride (halves)

    __half* Ws  = (__half*)smem;                                   // [NGC][WP] resident weights
    __half* Ab  = (__half*)(smem + (size_t)NGC * WP * 2);          // 2 x [128][72] A chunk buffers
    float*  gsm = (float*)(smem + (size_t)NGC * WP * 2 + 2 * 128 * 72 * 2); // [128][36] gates
    float*  cS  = gsm + 128 * 36;                                  // [128][8] cell state

    const int tid  = threadIdx.x;
    const int warp = tid >> 5, lane = tid & 31;
    const int wm = warp >> 1, wn = warp & 1;

    // Load resident weight slice: local row nl -> global gate col (nl/8)*512 + q*8 + (nl%8)
    {
        const __half* Wg = (LAYER == 0) ? g_W0 : g_W1;
        const int V = K / 8; // uint4 per row
        for (int i = tid; i < NGC * V; i += 256) {
            int nl = i / V, v = i - nl * V;
            int ng = (nl >> 3) * 512 + q * 8 + (nl & 7);
            *(uint4*)&Ws[nl * WP + v * 8] = *(const uint4*)&Wg[ng * K + v * 8];
        }
    }
    // Load cell-state slice (fp32, lives in smem for the whole run)
    for (int i = tid; i < 128 * 8; i += 256) {
        int b = i >> 3, jj = i & 7;
        cS[i] = c0[LAYER * B_ * H_ + b * H_ + q * 8 + jj];
    }
    __syncthreads();

    unsigned gen = 0;
    for (int s = 0; s <= T_; s++) {
        const bool active = (LAYER == 0) ? (s < T_) : (s >= 1);
        if (active) {
            const int t = (LAYER == 0) ? s : (s - 1);
            const __half* hprev = g_h0buf + ((unsigned)(s + 1) & 1u) * (B_ * H_);

            float acc[2][2][4];
            #pragma unroll
            for (int mi = 0; mi < 2; mi++)
                #pragma unroll
                for (int ni = 0; ni < 2; ni++)
                    #pragma unroll
                    for (int r = 0; r < 4; r++) acc[mi][ni][r] = 0.0f;

            auto load_chunk = [&](int c) {
                const __half* src; int stride;
                if (LAYER == 0) {
                    if (c < 2) { src = g_xT + (size_t)t * (B_ * D_) + c * 64; stride = D_; }
                    else       { src = hprev + (c * 64 - 128);               stride = H_; }
                } else {
                    if (c < 8) { src = hprev + c * 64;                                stride = H_; }
                    else       { src = g_h1seq + (size_t)t * (B_ * H_) + (c * 64 - 512); stride = H_; }
                }
                __half* dst = Ab + (c & 1) * (128 * 72);
                #pragma unroll
                for (int j = 0; j < 4; j++) {
                    int i = tid + j * 256;
                    int row = i >> 3, seg = i & 7;
                    cp16(dst + row * 72 + seg * 8, src + (size_t)row * stride + seg * 8);
                }
                cp_commit();
            };

            load_chunk(0);
            for (int c = 0; c < NC; c++) {
                if (c + 1 < NC) { load_chunk(c + 1); cp_wait1(); }
                else            { cp_wait0(); }
                __syncthreads();
                const __half* A = Ab + (c & 1) * (128 * 72);
                #pragma unroll
                for (int kk = 0; kk < 4; kk++) {
                    unsigned af[2][4], bf2[2][2];
                    #pragma unroll
                    for (int mi = 0; mi < 2; mi++) {
                        int r = wm * 32 + mi * 16 + (lane >> 2);
                        int ci = kk * 16 + (lane & 3) * 2;
                        af[mi][0] = *(const unsigned*)&A[r * 72 + ci];
                        af[mi][1] = *(const unsigned*)&A[(r + 8) * 72 + ci];
                        af[mi][2] = *(const unsigned*)&A[r * 72 + ci + 8];
                        af[mi][3] = *(const unsigned*)&A[(r + 8) * 72 + ci + 8];
                    }
                    #pragma unroll
                    for (int ni = 0; ni < 2; ni++) {
                        int n  = wn * 16 + ni * 8 + (lane >> 2);
                        int kg = c * 64 + kk * 16 + (lane & 3) * 2;
                        bf2[ni][0] = *(const unsigned*)&Ws[n * WP + kg];
                        bf2[ni][1] = *(const unsigned*)&Ws[n * WP + kg + 8];
                    }
                    #pragma unroll
                    for (int mi = 0; mi < 2; mi++)
                        #pragma unroll
                        for (int ni = 0; ni < 2; ni++)
                            mma_f16(acc[mi][ni], af[mi], bf2[ni]);
                }
                __syncthreads();
            }

            // Stage gates to smem (fp32)
            #pragma unroll
            for (int mi = 0; mi < 2; mi++)
                #pragma unroll
                for (int ni = 0; ni < 2; ni++) {
                    int r  = wm * 32 + mi * 16 + (lane >> 2);
                    int co = wn * 16 + ni * 8 + (lane & 3) * 2;
                    *(float2*)&gsm[r * 36 + co]       = make_float2(acc[mi][ni][0], acc[mi][ni][1]);
                    *(float2*)&gsm[(r + 8) * 36 + co] = make_float2(acc[mi][ni][2], acc[mi][ni][3]);
                }
            __syncthreads();

            // Elementwise cell update; write new h (fp16) to global
            __half* hdst = (LAYER == 0)
                ? (g_h0buf + ((unsigned)s & 1u) * (B_ * H_) + q * 8)
                : (g_h1seq + (size_t)(t + 1) * (B_ * H_) + q * 8);
            #pragma unroll
            for (int rep = 0; rep < 4; rep++) {
                int idx = tid + rep * 256;
                int b = idx >> 3, jj = idx & 7;
                float gi = gsm[b * 36 + jj];
                float gf = gsm[b * 36 + 8 + jj];
                float gg = gsm[b * 36 + 16 + jj];
                float go = gsm[b * 36 + 24 + jj];
                float cold = cS[b * 8 + jj];
                float cn = sigf(gf) * cold + sigf(gi) * tanhf(gg);
                cS[b * 8 + jj] = cn;
                hdst[b * H_ + jj] = __float2half(sigf(go) * tanhf(cn));
            }
        }

        // -------- grid barrier (custom spin; all NCTA CTAs every tick) --------
        __threadfence();
        __syncthreads();
        if (tid == 0) {
            unsigned arr = atomicAdd(&g_bar_count, 1u);
            if (arr == NCTA - 1) {
                atomicExch(&g_bar_count, 0u);
                __threadfence();
                atomicAdd(&g_bar_phase, 1u);
            } else {
                unsigned target = gen + 1;
                while ((int)(*(volatile unsigned*)&g_bar_phase) - (int)target < 0) { }
            }
        }
        gen++;
        __syncthreads();
    }
}

__global__ void __launch_bounds__(256, 1) lstm86_recur(const float* __restrict__ c0)
{
    extern __shared__ char smem[];
    if (blockIdx.x < NL) lstm86_role<0>(blockIdx.x, c0, smem);
    else                 lstm86_role<1>(blockIdx.x - NL, c0, smem);
}

// ---------------- output projection: out[b][t][:] = h1[t][b][:] @ Wout^T + b ----------------
__global__ void __launch_bounds__(256, 1) lstm86_out(const float* __restrict__ b_out,
                                                     float* __restrict__ out)
{
    extern __shared__ char smem[];
    __half* Ws    = (__half*)smem;                          // [128][520]
    __half* Ab    = (__half*)(smem + 128 * 520 * 2);        // 2 x [128][72]
    float*  biasS = (float*)(smem + 128 * 520 * 2 + 2 * 128 * 72 * 2);

    const int t = blockIdx.x;
    const int tid = threadIdx.x, warp = tid >> 5, lane = tid & 31;
    const int wm = warp >> 1, wn = warp & 1;

    for (int i = tid; i < 128 * 64; i += 256) {             // 64 uint4 per row
        int n = i >> 6, v = i & 63;
        *(uint4*)&Ws[n * 520 + v * 8] = *(const uint4*)&g_Wout[n * 512 + v * 8];
    }
    for (int i = tid; i < 128; i += 256) biasS[i] = b_out[i];
    __syncthreads();

    const __half* Asrc = g_h1seq + (size_t)(t + 1) * (B_ * H_);

    float acc[2][8][4];
    #pragma unroll
    for (int mi = 0; mi < 2; mi++)
        #pragma unroll
        for (int ni = 0; ni < 8; ni++)
            #pragma unroll
            for (int r = 0; r < 4; r++) acc[mi][ni][r] = 0.0f;

    auto load_chunk = [&](int c) {
        __half* dst = Ab + (c & 1) * (128 * 72);
        #pragma unroll
        for (int j = 0; j < 4; j++) {
            int i = tid + j * 256;
            int row = i >> 3, seg = i & 7;
            cp16(dst + row * 72 + seg * 8, Asrc + (size_t)row * H_ + c * 64 + seg * 8);
        }
        cp_commit();
    };

    load_chunk(0);
    for (int c = 0; c < 8; c++) {
        if (c < 7) { load_chunk(c + 1); cp_wait1(); }
        else       { cp_wait0(); }
        __syncthreads();
        const __half* A = Ab + (c & 1) * (128 * 72);
        #pragma unroll
        for (int kk = 0; kk < 4; kk++) {
            unsigned af[2][4], bf2[8][2];
            #pragma unroll
            for (int mi = 0; mi < 2; mi++) {
                int r = wm * 32 + mi * 16 + (lane >> 2);
                int ci = kk * 16 + (lane & 3) * 2;
                af[mi][0] = *(const unsigned*)&A[r * 72 + ci];
                af[mi][1] = *(const unsigned*)&A[(r + 8) * 72 + ci];
                af[mi][2] = *(const unsigned*)&A[r * 72 + ci + 8];
                af[mi][3] = *(const unsigned*)&A[(r + 8) * 72 + ci + 8];
            }
            #pragma unroll
            for (int ni = 0; ni < 8; ni++) {
                int n  = wn * 64 + ni * 8 + (lane >> 2);
                int kg = c * 64 + kk * 16 + (lane & 3) * 2;
                bf2[ni][0] = *(const unsigned*)&Ws[n * 520 + kg];
                bf2[ni][1] = *(const unsigned*)&Ws[n * 520 + kg + 8];
            }
            #pragma unroll
            for (int mi = 0; mi < 2; mi++)
                #pragma unroll
                for (int ni = 0; ni < 8; ni++)
                    mma_f16(acc[mi][ni], af[mi], bf2[ni]);
        }
        __syncthreads();
    }

    #pragma unroll
    for (int mi = 0; mi < 2; mi++)
        #pragma unroll
        for (int ni = 0; ni < 8; ni++) {
            int r  = wm * 32 + mi * 16 + (lane >> 2);
            int co = wn * 64 + ni * 8 + (lane & 3) * 2;
            float b0 = biasS[co], b1 = biasS[co + 1];
            size_t o0 = (size_t)r * (T_ * O_) + (size_t)t * O_ + co;
            size_t o1 = (size_t)(r + 8) * (T_ * O_) + (size_t)t * O_ + co;
            *(float2*)&out[o0] = make_float2(acc[mi][ni][0] + b0, acc[mi][ni][1] + b1);
            *(float2*)&out[o1] = make_float2(acc[mi][ni][2] + b0, acc[mi][ni][3] + b1);
        }
}

// ---------------- launch ----------------
#define SMEM_LSTM (32 * 1032 * 2 + 2 * 128 * 72 * 2 + 128 * 36 * 4 + 128 * 8 * 4) // 125440
#define SMEM_OUT  (128 * 520 * 2 + 2 * 128 * 72 * 2 + 128 * 4)                    // 170496

extern "C" void kernel_launch(void* const* d_in, const int* in_sizes, int n_in,
                              void* d_out, int out_size)
{
    const float* x    = (const float*)d_in[0];
    const float* h0   = (const float*)d_in[1];
    const float* c0   = (const float*)d_in[2];
    const float* wih0 = (const float*)d_in[3];
    const float* whh0 = (const float*)d_in[4];
    const float* wih1 = (const float*)d_in[5];
    const float* whh1 = (const float*)d_in[6];
    const float* wout = (const float*)d_in[7];
    const float* bout = (const float*)d_in[8];

    cudaFuncSetAttribute(lstm86_recur, cudaFuncAttributeMaxDynamicSharedMemorySize, SMEM_LSTM);
    cudaFuncSetAttribute(lstm86_out,   cudaFuncAttributeMaxDynamicSharedMemorySize, SMEM_OUT);

    lstm86_prep<<<1024, 256>>>(x, h0, wih0, whh0, wih1, whh1, wout);
    lstm86_recur<<<NCTA, 256, SMEM_LSTM>>>(c0);
    lstm86_out<<<T_, 256, SMEM_OUT>>>(bout, (float*)d_out);
}

// round 3
// speedup vs baseline: 1.3999x; 1.3999x over previous
#include <cuda_runtime.h>
#include <cuda_fp16.h>
#include <cstdint>

// Problem dims
#define T_  512
#define B_  128
#define D_  128
#define H_  512
#define O_  128
#define G4H 2048

#define NL    64          // CTAs per layer
#define NCTA  128         // total persistent CTAs

// ---------------- static device buffers ----------------
__device__ __align__(16) __half  g_xT[T_ * B_ * D_];          // x transposed [t][b][d], fp16
__device__ __align__(16) __half  g_W0[G4H * 640];             // [n][k]: k<128 = w_ih_0, else w_hh_0
__device__ __align__(16) __half  g_W1[G4H * 1024];            // [n][k]: k<512 = w_ih_1, else w_hh_1
__device__ __align__(16) __half  g_h0buf[2 * B_ * H_];        // double-buffered layer0 h
__device__ __align__(16) __half  g_h1seq[(T_ + 1) * B_ * H_]; // [t+1][b][k]; [0] = init
__device__ __align__(16) __half  g_Wout[O_ * H_];             // [o][k]
__device__ unsigned g_bar_count;
__device__ unsigned g_bar_phase;

// ---------------- SMEM layout for recur kernel ----------------
// B resident: up to 16 chunks x (32 rows x 144B) = 73728 B
// A stages:   4 stages x (128 rows x 144B) = 73728 B
#define BCHUNK_SZ 4608
#define A_OFF     73728
#define ASTAGE_SZ 18432
#define SMEM_LSTM (73728 + 4 * 18432)   // 147456

// ---------------- PTX helpers ----------------
__device__ __forceinline__ void mma_f16(float* c, const uint32_t* a, const uint32_t* b) {
    asm volatile(
        "mma.sync.aligned.m16n8k16.row.col.f32.f16.f16.f32 "
        "{%0,%1,%2,%3}, {%4,%5,%6,%7}, {%8,%9}, {%0,%1,%2,%3};"
        : "+f"(c[0]), "+f"(c[1]), "+f"(c[2]), "+f"(c[3])
        : "r"(a[0]), "r"(a[1]), "r"(a[2]), "r"(a[3]), "r"(b[0]), "r"(b[1]));
}
__device__ __forceinline__ void ldsm4(uint32_t* r, uint32_t addr) {
    asm volatile("ldmatrix.sync.aligned.m8n8.x4.shared.b16 {%0,%1,%2,%3}, [%4];"
                 : "=r"(r[0]), "=r"(r[1]), "=r"(r[2]), "=r"(r[3]) : "r"(addr));
}
__device__ __forceinline__ void cp16(uint32_t sdst, const void* gsrc) {
    asm volatile("cp.async.cg.shared.global [%0], [%1], 16;" :: "r"(sdst), "l"(gsrc));
}
__device__ __forceinline__ void cp_commit() { asm volatile("cp.async.commit_group;"); }
template <int N> __device__ __forceinline__ void cp_wait() { asm volatile("cp.async.wait_group %0;" :: "n"(N)); }

__device__ __forceinline__ float sigf(float x) {
    return __fdividef(1.0f, 1.0f + __expf(-x));
}
__device__ __forceinline__ float tanhe(float x) {
    return __fdividef(2.0f, 1.0f + __expf(-2.0f * x)) - 1.0f;
}

// ---------------- prep: layout conversion + barrier reset ----------------
__global__ void __launch_bounds__(256) lstm86_prep(
    const float* __restrict__ x, const float* __restrict__ h0,
    const float* __restrict__ wih0, const float* __restrict__ whh0,
    const float* __restrict__ wih1, const float* __restrict__ whh1,
    const float* __restrict__ wout)
{
    const int tid = blockIdx.x * blockDim.x + threadIdx.x;
    const int nt  = gridDim.x * blockDim.x;

    for (int i = tid; i < T_ * B_ * D_; i += nt) {
        int t = i >> 14; int r = i & 16383; int b = r >> 7; int d = r & 127;
        g_xT[i] = __float2half(x[(size_t)b * (T_ * D_) + t * D_ + d]);
    }
    for (int i = tid; i < G4H * 640; i += nt) {
        int n = i / 640, k = i - n * 640;
        float v = (k < 128) ? wih0[n * 128 + k] : whh0[n * 512 + (k - 128)];
        g_W0[i] = __float2half(v);
    }
    for (int i = tid; i < G4H * 1024; i += nt) {
        int n = i >> 10, k = i & 1023;
        float v = (k < 512) ? wih1[n * 512 + k] : whh1[n * 512 + (k - 512)];
        g_W1[i] = __float2half(v);
    }
    for (int i = tid; i < O_ * H_; i += nt) g_Wout[i] = __float2half(wout[i]);
    for (int i = tid; i < B_ * H_; i += nt) {
        g_h0buf[B_ * H_ + i] = __float2half(h0[i]);           // buffer 1 = layer0 init h
        g_h1seq[i]           = __float2half(h0[B_ * H_ + i]); // h1seq[0] = layer1 init h
    }
    if (tid == 0) { g_bar_count = 0; g_bar_phase = 0; }
}

// ---------------- persistent recurrent kernel (mma.sync, 128 threads) ----------------
template <int LAYER>
__device__ void lstm86_role(int q, const float* __restrict__ c0, char* smem)
{
    constexpr int K  = (LAYER == 0) ? 640 : 1024;
    constexpr int NC = K / 64;        // 64-K chunks: 10 or 16
    const int tid  = threadIdx.x;
    const int warp = tid >> 5, lane = tid & 31;
    const uint32_t sb = (uint32_t)__cvta_generic_to_shared(smem);

    // ---- load resident weights: [kc][32 n][72 halves]; local n = gate*8 + jj ----
    {
        const __half* Wg = (LAYER == 0) ? g_W0 : g_W1;
        for (int i = tid; i < NC * 256; i += 128) {
            int kc = i >> 8; int rem = i & 255; int n = rem >> 3; int s = rem & 7;
            int ng = (n >> 3) * 512 + q * 8 + (n & 7);
            *(uint4*)(smem + kc * BCHUNK_SZ + n * 144 + s * 16) =
                *(const uint4*)&Wg[(size_t)ng * K + kc * 64 + s * 8];
        }
    }
    __syncthreads();

    // ---- per-thread invariant fragment addressing ----
    // A: rows m = warp*32 + mi*16 + (lane&15); k half-offset = ((lane>>4)&1)*8
    const uint32_t a_row  = (uint32_t)(warp * 32 + (lane & 15));
    const uint32_t a_koff = (uint32_t)(((lane >> 4) & 1) * 8);
    // B: row n = pair*16 + ((lane>>4)&1)*8 + (lane&7); k half-offset = ((lane>>3)&1)*8
    const uint32_t b_row  = (uint32_t)(((lane >> 4) & 1) * 8 + (lane & 7));
    const uint32_t b_koff = (uint32_t)(((lane >> 3) & 1) * 8);

    // ---- cell state in registers: [mi][half][col 0/1] ----
    const int rrow0 = warp * 32 + (lane >> 2);   // mi=0, half=0 row
    const int jcol  = q * 8 + (lane & 3) * 2;    // global h-col (2 consecutive)
    float creg[2][2][2];
    #pragma unroll
    for (int mi = 0; mi < 2; mi++)
        #pragma unroll
        for (int hf = 0; hf < 2; hf++) {
            int r = rrow0 + mi * 16 + hf * 8;
            creg[mi][hf][0] = c0[LAYER * B_ * H_ + (size_t)r * H_ + jcol];
            creg[mi][hf][1] = c0[LAYER * B_ * H_ + (size_t)r * H_ + jcol + 1];
        }

    unsigned gen = 0;
    for (int s = 0; s <= T_; s++) {
        const bool active = (LAYER == 0) ? (s < T_) : (s >= 1);
        if (active) {
            const int t = (LAYER == 0) ? s : (s - 1);
            const __half* hprev = g_h0buf + ((unsigned)(s + 1) & 1u) * (B_ * H_);

            auto load_chunk = [&](int c) {
                const __half* srcb; int stride, col0;
                if (LAYER == 0) {
                    if (c < 2) { srcb = g_xT + (size_t)t * (B_ * D_); stride = D_; col0 = c * 64; }
                    else       { srcb = hprev; stride = H_; col0 = (c - 2) * 64; }
                } else {
                    if (c < 8) { srcb = hprev; stride = H_; col0 = c * 64; }
                    else       { srcb = g_h1seq + (size_t)t * (B_ * H_); stride = H_; col0 = (c - 8) * 64; }
                }
                uint32_t SA = sb + A_OFF + (uint32_t)(c & 3) * ASTAGE_SZ;
                #pragma unroll
                for (int jj = 0; jj < 8; jj++) {
                    int i = tid + jj * 128;           // 0..1023
                    int row = i >> 3, seg = i & 7;
                    cp16(SA + (uint32_t)row * 144 + (uint32_t)seg * 16,
                         srcb + (size_t)row * stride + col0 + seg * 8);
                }
                cp_commit();
            };

            float acc[2][4][4];
            #pragma unroll
            for (int mi = 0; mi < 2; mi++)
                #pragma unroll
                for (int n8 = 0; n8 < 4; n8++)
                    #pragma unroll
                    for (int r = 0; r < 4; r++) acc[mi][n8][r] = 0.0f;

            load_chunk(0); load_chunk(1); load_chunk(2);

            #pragma unroll
            for (int c = 0; c < NC; c++) {
                if (c + 2 < NC)      cp_wait<2>();
                else if (c + 1 < NC) cp_wait<1>();
                else                 cp_wait<0>();
                __syncthreads();

                const uint32_t SA = sb + A_OFF + (uint32_t)(c & 3) * ASTAGE_SZ;
                const uint32_t BC = sb + (uint32_t)c * BCHUNK_SZ;
                #pragma unroll
                for (int kk = 0; kk < 4; kk++) {
                    uint32_t a0[4], a1[4], b0[4], b1[4];
                    uint32_t kbase = (uint32_t)(kk * 16) * 2;
                    ldsm4(a0, SA + (a_row)       * 144 + kbase + a_koff * 2);
                    ldsm4(a1, SA + (a_row + 16)  * 144 + kbase + a_koff * 2);
                    ldsm4(b0, BC + (b_row)       * 144 + kbase + b_koff * 2);
                    ldsm4(b1, BC + (b_row + 16)  * 144 + kbase + b_koff * 2);
                    mma_f16(acc[0][0], a0, b0);     mma_f16(acc[0][1], a0, b0 + 2);
                    mma_f16(acc[0][2], a0, b1);     mma_f16(acc[0][3], a0, b1 + 2);
                    mma_f16(acc[1][0], a1, b0);     mma_f16(acc[1][1], a1, b0 + 2);
                    mma_f16(acc[1][2], a1, b1);     mma_f16(acc[1][3], a1, b1 + 2);
                }
                if (c + 3 < NC) load_chunk(c + 3);
            }

            // ---- register epilogue: n8 groups are the 4 gates for this thread's cols ----
            __half* hdst = (LAYER == 0)
                ? (g_h0buf + ((unsigned)s & 1u) * (B_ * H_))
                : (g_h1seq + (size_t)(t + 1) * (B_ * H_));
            #pragma unroll
            for (int mi = 0; mi < 2; mi++)
                #pragma unroll
                for (int hf = 0; hf < 2; hf++) {
                    int r = rrow0 + mi * 16 + hf * 8;
                    float h2[2];
                    #pragma unroll
                    for (int cs = 0; cs < 2; cs++) {
                        float gi = acc[mi][0][hf * 2 + cs];
                        float gf = acc[mi][1][hf * 2 + cs];
                        float gg = acc[mi][2][hf * 2 + cs];
                        float go = acc[mi][3][hf * 2 + cs];
                        float cn = sigf(gf) * creg[mi][hf][cs] + sigf(gi) * tanhe(gg);
                        creg[mi][hf][cs] = cn;
                        h2[cs] = sigf(go) * tanhe(cn);
                    }
                    __half2 p = __floats2half2_rn(h2[0], h2[1]);
                    *(__half2*)(hdst + (size_t)r * H_ + jcol) = p;
                }
        }

        // -------- grid barrier --------
        __threadfence();
        __syncthreads();
        if (tid == 0) {
            unsigned arr = atomicAdd(&g_bar_count, 1u);
            if (arr == NCTA - 1) {
                atomicExch(&g_bar_count, 0u);
                __threadfence();
                atomicAdd(&g_bar_phase, 1u);
            } else {
                unsigned target = gen + 1;
                while ((int)(*(volatile unsigned*)&g_bar_phase) - (int)target < 0) { }
            }
        }
        gen++;
        __syncthreads();
    }
}

__global__ void __launch_bounds__(128, 1) lstm86_recur(const float* __restrict__ c0)
{
    extern __shared__ char smem[];
    if (blockIdx.x < NL) lstm86_role<0>(blockIdx.x, c0, smem);
    else                 lstm86_role<1>(blockIdx.x - NL, c0, smem);
}

// ---------------- output projection: out[b][t][:] = h1[t][b][:] @ Wout^T + b ----------------
__global__ void __launch_bounds__(256, 1) lstm86_out(const float* __restrict__ b_out,
                                                     float* __restrict__ out)
{
    extern __shared__ char smem[];
    __half* Ws    = (__half*)smem;                          // [128][520]
    __half* Ab    = (__half*)(smem + 128 * 520 * 2);        // 2 x [128][72]
    float*  biasS = (float*)(smem + 128 * 520 * 2 + 2 * 128 * 72 * 2);

    const int t = blockIdx.x;
    const int tid = threadIdx.x, warp = tid >> 5, lane = tid & 31;
    const int wm = warp >> 1, wn = warp & 1;

    for (int i = tid; i < 128 * 64; i += 256) {
        int n = i >> 6, v = i & 63;
        *(uint4*)&Ws[n * 520 + v * 8] = *(const uint4*)&g_Wout[n * 512 + v * 8];
    }
    for (int i = tid; i < 128; i += 256) biasS[i] = b_out[i];
    __syncthreads();

    const __half* Asrc = g_h1seq + (size_t)(t + 1) * (B_ * H_);

    float acc[2][8][4];
    #pragma unroll
    for (int mi = 0; mi < 2; mi++)
        #pragma unroll
        for (int ni = 0; ni < 8; ni++)
            #pragma unroll
            for (int r = 0; r < 4; r++) acc[mi][ni][r] = 0.0f;

    auto load_chunk = [&](int c) {
        __half* dst = Ab + (c & 1) * (128 * 72);
        #pragma unroll
        for (int j = 0; j < 4; j++) {
            int i = tid + j * 256;
            int row = i >> 3, seg = i & 7;
            uint32_t sa = (uint32_t)__cvta_generic_to_shared(dst + row * 72 + seg * 8);
            asm volatile("cp.async.cg.shared.global [%0], [%1], 16;"
                         :: "r"(sa), "l"(Asrc + (size_t)row * H_ + c * 64 + seg * 8));
        }
        cp_commit();
    };

    load_chunk(0);
    for (int c = 0; c < 8; c++) {
        if (c < 7) { load_chunk(c + 1); cp_wait<1>(); }
        else       { cp_wait<0>(); }
        __syncthreads();
        const __half* A = Ab + (c & 1) * (128 * 72);
        #pragma unroll
        for (int kk = 0; kk < 4; kk++) {
            uint32_t af[2][4], bf2[8][2];
            #pragma unroll
            for (int mi = 0; mi < 2; mi++) {
                int r = wm * 32 + mi * 16 + (lane >> 2);
                int ci = kk * 16 + (lane & 3) * 2;
                af[mi][0] = *(const uint32_t*)&A[r * 72 + ci];
                af[mi][1] = *(const uint32_t*)&A[(r + 8) * 72 + ci];
                af[mi][2] = *(const uint32_t*)&A[r * 72 + ci + 8];
                af[mi][3] = *(const uint32_t*)&A[(r + 8) * 72 + ci + 8];
            }
            #pragma unroll
            for (int ni = 0; ni < 8; ni++) {
                int n  = wn * 64 + ni * 8 + (lane >> 2);
                int kg = c * 64 + kk * 16 + (lane & 3) * 2;
                bf2[ni][0] = *(const uint32_t*)&Ws[n * 520 + kg];
                bf2[ni][1] = *(const uint32_t*)&Ws[n * 520 + kg + 8];
            }
            #pragma unroll
            for (int mi = 0; mi < 2; mi++)
                #pragma unroll
                for (int ni = 0; ni < 8; ni++)
                    mma_f16(acc[mi][ni], af[mi], bf2[ni]);
        }
        __syncthreads();
    }

    #pragma unroll
    for (int mi = 0; mi < 2; mi++)
        #pragma unroll
        for (int ni = 0; ni < 8; ni++) {
            int r  = wm * 32 + mi * 16 + (lane >> 2);
            int co = wn * 64 + ni * 8 + (lane & 3) * 2;
            float b0 = biasS[co], b1 = biasS[co + 1];
            size_t o0 = (size_t)r * (T_ * O_) + (size_t)t * O_ + co;
            size_t o1 = (size_t)(r + 8) * (T_ * O_) + (size_t)t * O_ + co;
            *(float2*)&out[o0] = make_float2(acc[mi][ni][0] + b0, acc[mi][ni][1] + b1);
            *(float2*)&out[o1] = make_float2(acc[mi][ni][2] + b0, acc[mi][ni][3] + b1);
        }
}

// ---------------- launch ----------------
#define SMEM_OUT  (128 * 520 * 2 + 2 * 128 * 72 * 2 + 128 * 4)

extern "C" void kernel_launch(void* const* d_in, const int* in_sizes, int n_in,
                              void* d_out, int out_size)
{
    const float* x    = (const float*)d_in[0];
    const float* h0   = (const float*)d_in[1];
    const float* c0   = (const float*)d_in[2];
    const float* wih0 = (const float*)d_in[3];
    const float* whh0 = (const float*)d_in[4];
    const float* wih1 = (const float*)d_in[5];
    const float* whh1 = (const float*)d_in[6];
    const float* wout = (const float*)d_in[7];
    const float* bout = (const float*)d_in[8];

    cudaFuncSetAttribute(lstm86_recur, cudaFuncAttributeMaxDynamicSharedMemorySize, SMEM_LSTM);
    cudaFuncSetAttribute(lstm86_out,   cudaFuncAttributeMaxDynamicSharedMemorySize, SMEM_OUT);

    lstm86_prep<<<1024, 256>>>(x, h0, wih0, whh0, wih1, whh1, wout);
    lstm86_recur<<<NCTA, 128, SMEM_LSTM>>>(c0);
    lstm86_out<<<T_, 256, SMEM_OUT>>>(bout, (float*)d_out);
}